// round 4
// baseline (speedup 1.0000x reference)
#include <cuda_runtime.h>
#include <cstdint>

#define RDIM 64
#define ODIM 256
#define IDIM 256
#define ENT  128      // entities per main block

typedef unsigned long long u64;

__device__ u64 g_Wdup[RDIM * ODIM];   // (Wsum, Wsum) duplicated pairs, 128 KB (L2)

__device__ __forceinline__ float frcp_approx(float a) {
    float r; asm("rcp.approx.f32 %0, %1;" : "=f"(r) : "f"(a)); return r;
}
__device__ __forceinline__ u64 ffma2(u64 a, u64 b, u64 c) {
    u64 d; asm("fma.rn.f32x2 %0, %1, %2, %3;" : "=l"(d) : "l"(a), "l"(b), "l"(c)); return d;
}
__device__ __forceinline__ u64 fmul2(u64 a, u64 b) {
    u64 d; asm("mul.rn.f32x2 %0, %1, %2;" : "=l"(d) : "l"(a), "l"(b)); return d;
}
__device__ __forceinline__ u64 pack2(float lo, float hi) {
    u64 d; asm("mov.b64 %0, {%1, %2};" : "=l"(d) : "f"(lo), "f"(hi)); return d;
}
__device__ __forceinline__ void unpack2(u64 v, float& lo, float& hi) {
    asm("mov.b64 {%0, %1}, %2;" : "=f"(lo), "=f"(hi) : "l"(v));
}

// ---------------------------------------------------------------------------
// Kernel 1: W_sum[r][o] = sum_i W[r][i][o], stored as DUPLICATED (v,v) u64
// pairs so main can LDG.64 straight into FFMA2 operand pairs.
// Grid (64 r, 4 o-tiles) x 256 threads.
// ---------------------------------------------------------------------------
__global__ void wsum_kernel(const float* __restrict__ W) {
    __shared__ float s[4][64];
    int r  = blockIdx.x;
    int ot = blockIdx.y;
    int oc = threadIdx.x & 63;
    int q  = threadIdx.x >> 6;
    int o  = ot * 64 + oc;
    const float* p = W + (size_t)r * IDIM * ODIM + (size_t)(q * 64) * ODIM + o;
    float acc = 0.f;
    #pragma unroll 16
    for (int i = 0; i < 64; i++) acc += p[(size_t)i * ODIM];
    s[q][oc] = acc;
    __syncthreads();
    if (q == 0) {
        float v = (s[0][oc] + s[1][oc]) + (s[2][oc] + s[3][oc]);
        g_Wdup[r * ODIM + o] = pack2(v, v);
    }
}

// ---------------------------------------------------------------------------
// Kernel 2 (main): out[e][o] = x_sum[e] * sum_r rcp_cs[e][r] * Wsum[r][o]
// f32x2 packed over ENTITIES: thread t owns output column t; per 4-entity
// group it runs 2 acc chains (e0,e1) and (e2,e3) sharing the same w[r]
// duplicated register pair. Inner loop: 64 LDS.128 + 128 FFMA2 per warp per
// 4 entities (LDS:FFMA2 = 1:2, half the previous crossbar traffic).
// s_rcp is [r][ENT] so LDS offsets are immediates; staging transpose is
// conflict-free (lanes write consecutive entities -> distinct banks).
// ---------------------------------------------------------------------------
__global__ __launch_bounds__(256) void rgcn_main_kernel(
        const float* __restrict__ x, const float* __restrict__ cs,
        float* __restrict__ out, int E) {
    __shared__ float s_rcp[RDIM][ENT];    // 32 KB, [r][entity]
    __shared__ float s_xs[ENT];
    int t = threadIdx.x;
    int e0 = blockIdx.x * ENT;

    // --- W column t: 64 duplicated u64 pairs from L2-resident table ---
    u64 w[RDIM];
    #pragma unroll
    for (int r = 0; r < RDIM; r++)
        w[r] = __ldg(&g_Wdup[r * ODIM + t]);

    // --- stage rcp(cs) transposed: thread = (entity e, r-half rh) ---
    {
        int e  = t & 127;
        int rh = (t >> 7) * 32;           // 0 or 32
        bool valid = (e0 + e) < E;
        const float4* row = (const float4*)(cs + (size_t)(e0 + e) * RDIM + rh);
        #pragma unroll
        for (int k = 0; k < 8; k++) {
            float4 v = make_float4(1.f, 1.f, 1.f, 1.f);
            if (valid) v = row[k];
            int r = rh + k * 4;
            s_rcp[r + 0][e] = frcp_approx(v.x);   // STS.32: lanes -> consecutive e
            s_rcp[r + 1][e] = frcp_approx(v.y);   // -> distinct banks, no conflict
            s_rcp[r + 2][e] = frcp_approx(v.z);
            s_rcp[r + 3][e] = frcp_approx(v.w);
        }
    }

    // --- fused xsum: warp w reduces rows 16w..16w+15 ---
    {
        int wid = t >> 5, lane = t & 31;
        #pragma unroll 4
        for (int rr = 0; rr < 16; rr++) {
            int e = wid * 16 + rr;
            float s = 0.f;
            if (e0 + e < E) {
                const float4* row = (const float4*)(x + (size_t)(e0 + e) * IDIM);
                float4 a = row[lane];
                float4 b = row[lane + 32];
                s = ((a.x + a.y) + (a.z + a.w)) + ((b.x + b.y) + (b.z + b.w));
            }
            #pragma unroll
            for (int off = 16; off; off >>= 1)
                s += __shfl_xor_sync(0xffffffffu, s, off);
            if (lane == 0) s_xs[e] = s;
        }
    }
    __syncthreads();

    // --- mainloop: 32 groups of 4 entities ---
    #pragma unroll 1
    for (int g = 0; g < ENT / 4; g++) {
        u64 acc0 = 0ull, acc1 = 0ull;
        #pragma unroll
        for (int r = 0; r < RDIM; r++) {
            // LDS.128 broadcast: (rcp[e0][r], rcp[e1][r], rcp[e2][r], rcp[e3][r])
            ulonglong2 c = *(const ulonglong2*)&s_rcp[r][4 * g];
            acc0 = ffma2(c.x, w[r], acc0);
            acc1 = ffma2(c.y, w[r], acc1);
        }
        float2 xsa = *(const float2*)&s_xs[4 * g];
        float2 xsb = *(const float2*)&s_xs[4 * g + 2];
        u64 ra = fmul2(acc0, pack2(xsa.x, xsa.y));
        u64 rb = fmul2(acc1, pack2(xsb.x, xsb.y));
        float v0, v1, v2, v3;
        unpack2(ra, v0, v1);
        unpack2(rb, v2, v3);
        int e = e0 + 4 * g;
        if (e + 0 < E) out[(size_t)(e + 0) * ODIM + t] = v0;
        if (e + 1 < E) out[(size_t)(e + 1) * ODIM + t] = v1;
        if (e + 2 < E) out[(size_t)(e + 2) * ODIM + t] = v2;
        if (e + 3 < E) out[(size_t)(e + 3) * ODIM + t] = v3;
    }
}

// ---------------------------------------------------------------------------
extern "C" void kernel_launch(void* const* d_in, const int* in_sizes, int n_in,
                              void* d_out, int out_size) {
    const float* x  = (const float*)d_in[0];
    const float* cs = (const float*)d_in[1];
    const float* W  = (const float*)d_in[2];
    // d_in[3] (edge_index) is mathematically unused by the reference — skipped.
    float* out = (float*)d_out;
    int E = in_sizes[0] / IDIM;

    wsum_kernel<<<dim3(RDIM, 4), 256>>>(W);
    rgcn_main_kernel<<<(E + ENT - 1) / ENT, 256>>>(x, cs, out, E);
}

// round 6
// speedup vs baseline: 2.3071x; 2.3071x over previous
#include <cuda_runtime.h>
#include <cuda_bf16.h>
#include <cstdint>

typedef unsigned int u32;

#define RDIM 64
#define ODIM 256
#define IDIM 256
#define ENT  128

// smem byte offsets
#define SM_AH 0          // A-hi: 128 x 64 bf16, 128B rows, swizzled (16 KB)
#define SM_AL 16384      // A-lo                                  (16 KB)
#define SM_BH 32768      // B-hi: 256 x 64 bf16 (B^T), swizzled   (32 KB)
#define SM_BL 65536      // B-lo                                  (32 KB)
#define SM_XS 98304      // 128 f32 row sums
#define DYN_SMEM 98816

// B images pre-split + pre-swizzled by wsum_kernel: [hi/lo][o-row 128B image]
__device__ __nv_bfloat16 g_B[2][256 * 64];

__device__ __forceinline__ float frcp(float a) {
    float r; asm("rcp.approx.f32 %0, %1;" : "=f"(r) : "f"(a)); return r;
}
__device__ __forceinline__ u32 smem_u32(const void* p) {
    u32 a; asm("{ .reg .u64 t; cvta.to.shared.u64 t, %1; cvt.u32.u64 %0, t; }"
               : "=r"(a) : "l"(p)); return a;
}

#define LDSM4(r0, r1, r2, r3, addr) \
    asm volatile("ldmatrix.sync.aligned.m8n8.x4.shared.b16 {%0,%1,%2,%3}, [%4];" \
        : "=r"(r0), "=r"(r1), "=r"(r2), "=r"(r3) : "r"(addr))

#define MMA16816(d, a, b0, b1) \
    asm volatile("mma.sync.aligned.m16n8k16.row.col.f32.bf16.bf16.f32 " \
        "{%0,%1,%2,%3}, {%4,%5,%6,%7}, {%8,%9}, {%0,%1,%2,%3};" \
        : "+f"((d)[0]), "+f"((d)[1]), "+f"((d)[2]), "+f"((d)[3]) \
        : "r"((a)[0]), "r"((a)[1]), "r"((a)[2]), "r"((a)[3]), "r"(b0), "r"(b1))

// ---------------------------------------------------------------------------
// Kernel 1: Wsum[r][o] = sum_i W[r][i][o]; bf16 hi/lo split, scattered into
// the swizzled B^T smem image layout (row = o, 64 bf16 = 128 B per row).
// ---------------------------------------------------------------------------
__global__ void wsum_kernel(const float* __restrict__ W) {
    __shared__ float s[4][64];
    int r  = blockIdx.x;
    int ot = blockIdx.y;
    int oc = threadIdx.x & 63;
    int q  = threadIdx.x >> 6;
    int o  = ot * 64 + oc;
    const float* p = W + (size_t)r * IDIM * ODIM + (size_t)(q * 64) * ODIM + o;
    float acc = 0.f;
    #pragma unroll 16
    for (int i = 0; i < 64; i++) acc += p[(size_t)i * ODIM];
    s[q][oc] = acc;
    __syncthreads();
    if (q == 0) {
        float v = (s[0][oc] + s[1][oc]) + (s[2][oc] + s[3][oc]);
        __nv_bfloat16 bh = __float2bfloat16(v);
        __nv_bfloat16 bl = __float2bfloat16(v - __bfloat162float(bh));
        u32 off = ((u32)o * 128u + (((u32)r * 2u) ^ (((u32)o & 7u) << 4))) >> 1;
        g_B[0][off] = bh;
        g_B[1][off] = bl;
    }
}

// ---------------------------------------------------------------------------
// Kernel 2 (main, warp-level bf16 MMA):
//   out[128e x 256o] per CTA = A @ B,  A[e][r] = xsum[e] * rcp(cs[e][r]),
//   split-precision: D = Ah*Bh + Al*Bh + Ah*Bl (fp32 accum).
// 8 warps, grid 4(M) x 2(N): warp tile 32 rows x 128 cols (two 64-col halves
// processed sequentially, 64 f32 accums live at a time).
// ---------------------------------------------------------------------------
__global__ __launch_bounds__(256, 2) void rgcn_mma_kernel(
        const float* __restrict__ x, const float* __restrict__ cs,
        float* __restrict__ out, int E) {
    extern __shared__ char smp[];
    int t = threadIdx.x, warp = t >> 5, lane = t & 31;
    int e0 = blockIdx.x * ENT;
    float* sxs = (float*)(smp + SM_XS);

    // --- fused xsum: warp w reduces rows 16w..16w+15 ---
    {
        #pragma unroll 4
        for (int rr = 0; rr < 16; rr++) {
            int e = warp * 16 + rr;
            float s = 0.f;
            if (e0 + e < E) {
                const float4* row = (const float4*)(x + (size_t)(e0 + e) * IDIM);
                float4 a = row[lane];
                float4 b = row[lane + 32];
                s = ((a.x + a.y) + (a.z + a.w)) + ((b.x + b.y) + (b.z + b.w));
            }
            #pragma unroll
            for (int off = 16; off; off >>= 1)
                s += __shfl_xor_sync(0xffffffffu, s, off);
            if (lane == 0) sxs[e] = s;
        }
    }

    // --- B copy: 64 KB pre-swizzled hi+lo image, linear from L2 ---
    {
        const uint4* src = (const uint4*)g_B;
        uint4* dst = (uint4*)(smp + SM_BH);
        #pragma unroll
        for (int i = 0; i < 16; i++) dst[i * 256 + t] = src[i * 256 + t];
    }
    __syncthreads();

    // --- A build: thread -> (entity e, r-half); bf16 hi/lo, swizzled STS.64 ---
    {
        int e  = t & 127;
        int rh = (t >> 7) * 32;
        bool valid = (e0 + e) < E;
        float xs = sxs[e];
        const float4* crow = (const float4*)(cs + (size_t)(e0 + e) * RDIM + rh);
        char* ah = smp + SM_AH + e * 128;
        char* al = smp + SM_AL + e * 128;
        u32 sx = (u32)(e & 7) << 4;
        #pragma unroll
        for (int j = 0; j < 8; j++) {
            float4 c = valid ? crow[j] : make_float4(1.f, 1.f, 1.f, 1.f);
            float a0 = xs * frcp(c.x), a1 = xs * frcp(c.y);
            float a2 = xs * frcp(c.z), a3 = xs * frcp(c.w);
            __nv_bfloat162 h01 = __floats2bfloat162_rn(a0, a1);
            __nv_bfloat162 h23 = __floats2bfloat162_rn(a2, a3);
            __nv_bfloat162 l01 = __floats2bfloat162_rn(
                a0 - __bfloat162float(h01.x), a1 - __bfloat162float(h01.y));
            __nv_bfloat162 l23 = __floats2bfloat162_rn(
                a2 - __bfloat162float(h23.x), a3 - __bfloat162float(h23.y));
            u32 offs = (((u32)(rh + j * 4) * 2u) ^ sx);  // 8B-in-chunk preserved
            *(uint2*)(ah + offs) = make_uint2(*(u32*)&h01, *(u32*)&h23);
            *(uint2*)(al + offs) = make_uint2(*(u32*)&l01, *(u32*)&l23);
        }
    }
    __syncthreads();

    // --- MMA mainloop ---
    int wm = warp & 3, wn = warp >> 2;
    u32 abase[2] = { smem_u32(smp + SM_AH), smem_u32(smp + SM_AL) };
    u32 bbase[2] = { smem_u32(smp + SM_BH), smem_u32(smp + SM_BL) };
    const int PA[3] = {0, 1, 0}, PB[3] = {0, 0, 1};   // (Ah,Bh),(Al,Bh),(Ah,Bl)

    #pragma unroll 1
    for (int h = 0; h < 2; h++) {
        float d[2][8][4];
        #pragma unroll
        for (int mb = 0; mb < 2; mb++)
            #pragma unroll
            for (int nb = 0; nb < 8; nb++)
                #pragma unroll
                for (int q = 0; q < 4; q++) d[mb][nb][q] = 0.f;

        #pragma unroll 1
        for (int p = 0; p < 3; p++) {
            u32 ab = abase[PA[p]], bb = bbase[PB[p]];
            #pragma unroll
            for (int kb = 0; kb < 4; kb++) {
                // A frags: two m16k16 tiles (rows wm*32 + mb*16 + 0..15)
                u32 a[2][4];
                #pragma unroll
                for (int mb = 0; mb < 2; mb++) {
                    int row  = wm * 32 + mb * 16 + (lane & 15);
                    u32 colb = (u32)kb * 32 + ((u32)(lane >> 4) << 4);
                    u32 addr = ab + (u32)row * 128 + (colb ^ (((u32)row & 7u) << 4));
                    LDSM4(a[mb][0], a[mb][1], a[mb][2], a[mb][3], addr);
                }
                // B frags: 4 x ldmatrix.x4, each covers two n8 blocks (n16 x k16)
                u32 b[4][4];
                #pragma unroll
                for (int q = 0; q < 4; q++) {
                    int nrow = wn * 128 + h * 64 + q * 16 + ((lane >> 4) << 3) + (lane & 7);
                    u32 colb = (u32)kb * 32 + (((u32)(lane >> 3) & 1u) << 4);
                    u32 addr = bb + (u32)nrow * 128 + (colb ^ (((u32)nrow & 7u) << 4));
                    LDSM4(b[q][0], b[q][1], b[q][2], b[q][3], addr);
                }
                #pragma unroll
                for (int mb = 0; mb < 2; mb++)
                    #pragma unroll
                    for (int nb = 0; nb < 8; nb++)
                        MMA16816(d[mb][nb], a[mb],
                                 b[nb >> 1][(nb & 1) * 2],
                                 b[nb >> 1][(nb & 1) * 2 + 1]);
            }
        }

        // --- epilogue: direct STG.64 (32B row segments = full sectors) ---
        #pragma unroll
        for (int mb = 0; mb < 2; mb++) {
            int r0 = e0 + wm * 32 + mb * 16 + (lane >> 2);
            #pragma unroll
            for (int nb = 0; nb < 8; nb++) {
                int col = wn * 128 + h * 64 + nb * 8 + (lane & 3) * 2;
                if (r0 < E)
                    *(float2*)(out + (size_t)r0 * ODIM + col) =
                        make_float2(d[mb][nb][0], d[mb][nb][1]);
                if (r0 + 8 < E)
                    *(float2*)(out + (size_t)(r0 + 8) * ODIM + col) =
                        make_float2(d[mb][nb][2], d[mb][nb][3]);
            }
        }
    }
}

// ---------------------------------------------------------------------------
extern "C" void kernel_launch(void* const* d_in, const int* in_sizes, int n_in,
                              void* d_out, int out_size) {
    const float* x  = (const float*)d_in[0];
    const float* cs = (const float*)d_in[1];
    const float* W  = (const float*)d_in[2];
    // d_in[3] (edge_index) is mathematically unused by the reference — skipped.
    float* out = (float*)d_out;
    int E = in_sizes[0] / IDIM;

    cudaFuncSetAttribute(rgcn_mma_kernel,
                         cudaFuncAttributeMaxDynamicSharedMemorySize, DYN_SMEM);

    wsum_kernel<<<dim3(RDIM, 4), 256>>>(W);
    rgcn_mma_kernel<<<(E + ENT - 1) / ENT, 256, DYN_SMEM>>>(x, cs, out, E);
}

// round 7
// speedup vs baseline: 2.3920x; 1.0368x over previous
#include <cuda_runtime.h>
#include <cuda_bf16.h>
#include <cstdint>

typedef unsigned int u32;

#define RDIM 64
#define ODIM 256
#define IDIM 256
#define ENT  128

// smem byte offsets (main kernel)
#define SM_AH 0          // A-hi: 128 x 64 bf16, 128B rows, swizzled (16 KB)
#define SM_AL 16384      // A-lo                                  (16 KB)
#define SM_BH 32768      // B-hi: 256 x 64 bf16 (B^T), swizzled   (32 KB)
#define SM_BL 65536      // B-lo                                  (32 KB)
#define DYN_SMEM 98304

// B images pre-split + pre-swizzled by wsum_kernel: [hi/lo][o-row 128B image]
__device__ __nv_bfloat16 g_B[2][256 * 64];
__device__ float g_xsum[131072];

__device__ __forceinline__ float frcp(float a) {
    float r; asm("rcp.approx.f32 %0, %1;" : "=f"(r) : "f"(a)); return r;
}
__device__ __forceinline__ u32 smem_u32(const void* p) {
    u32 a; asm("{ .reg .u64 t; cvta.to.shared.u64 t, %1; cvt.u32.u64 %0, t; }"
               : "=r"(a) : "l"(p)); return a;
}

#define LDSM4(r0, r1, r2, r3, addr) \
    asm volatile("ldmatrix.sync.aligned.m8n8.x4.shared.b16 {%0,%1,%2,%3}, [%4];" \
        : "=r"(r0), "=r"(r1), "=r"(r2), "=r"(r3) : "r"(addr))

#define MMA16816(d, a, b0, b1) \
    asm volatile("mma.sync.aligned.m16n8k16.row.col.f32.bf16.bf16.f32 " \
        "{%0,%1,%2,%3}, {%4,%5,%6,%7}, {%8,%9}, {%0,%1,%2,%3};" \
        : "+f"((d)[0]), "+f"((d)[1]), "+f"((d)[2]), "+f"((d)[3]) \
        : "r"((a)[0]), "r"((a)[1]), "r"((a)[2]), "r"((a)[3]), "r"(b0), "r"(b1))

// ---------------------------------------------------------------------------
// Kernel 1: Wsum[r][o] = sum_i W[r][i][o]; bf16 hi/lo split, scattered into
// the swizzled B^T smem image layout (row = o, 64 bf16 = 128 B per row).
// ---------------------------------------------------------------------------
__global__ void wsum_kernel(const float* __restrict__ W) {
    __shared__ float s[4][64];
    int r  = blockIdx.x;
    int ot = blockIdx.y;
    int oc = threadIdx.x & 63;
    int q  = threadIdx.x >> 6;
    int o  = ot * 64 + oc;
    const float* p = W + (size_t)r * IDIM * ODIM + (size_t)(q * 64) * ODIM + o;
    float acc = 0.f;
    #pragma unroll 16
    for (int i = 0; i < 64; i++) acc += p[(size_t)i * ODIM];
    s[q][oc] = acc;
    __syncthreads();
    if (q == 0) {
        float v = (s[0][oc] + s[1][oc]) + (s[2][oc] + s[3][oc]);
        __nv_bfloat16 bh = __float2bfloat16(v);
        __nv_bfloat16 bl = __float2bfloat16(v - __bfloat162float(bh));
        u32 off = ((u32)o * 128u + (((u32)r * 2u) ^ (((u32)o & 7u) << 4))) >> 1;
        g_B[0][off] = bh;
        g_B[1][off] = bl;
    }
}

// ---------------------------------------------------------------------------
// Kernel 2: x_sum[e] = sum_j x[e][j]. Pure streaming: one warp per row,
// 2 x LDG.128 per lane, shfl reduce. ~102 MB at streaming bandwidth.
// ---------------------------------------------------------------------------
__global__ void xsum_kernel(const float* __restrict__ x, int E) {
    int e = (int)((blockIdx.x * (unsigned)blockDim.x + threadIdx.x) >> 5);
    int lane = threadIdx.x & 31;
    if (e >= E) return;
    const float4* row = (const float4*)(x + (size_t)e * IDIM);
    float4 a = row[lane];
    float4 b = row[lane + 32];
    float s = ((a.x + a.y) + (a.z + a.w)) + ((b.x + b.y) + (b.z + b.w));
    #pragma unroll
    for (int off = 16; off; off >>= 1) s += __shfl_xor_sync(0xffffffffu, s, off);
    if (lane == 0) g_xsum[e] = s;
}

// ---------------------------------------------------------------------------
// Kernel 3 (main, warp-level bf16 MMA):
//   out[128e x 256o] per CTA = A @ B,  A[e][r] = xsum[e] * rcp(cs[e][r]),
//   split-precision: D = Ah*Bh + Al*Bh + Ah*Bl (fp32 accum).
// 8 warps, 4(M) x 2(N): warp tile 32 rows x 128 cols, two 64-col halves.
// Frags held live across split passes: 12 LDSM.x4 per kb (was 18).
// ---------------------------------------------------------------------------
__global__ __launch_bounds__(256, 2) void rgcn_mma_kernel(
        const float* __restrict__ cs, float* __restrict__ out, int E) {
    extern __shared__ char smp[];
    int t = threadIdx.x, warp = t >> 5, lane = t & 31;
    int e0 = blockIdx.x * ENT;

    // --- B copy: 64 KB pre-swizzled hi+lo image, linear from L2 ---
    {
        const uint4* src = (const uint4*)g_B;
        uint4* dst = (uint4*)(smp + SM_BH);
        #pragma unroll
        for (int i = 0; i < 16; i++) dst[i * 256 + t] = src[i * 256 + t];
    }

    // --- A build: thread -> (row e = t>>1, interleaved float4 h + 2j) ---
    // Lane pairs read adjacent 16B -> full 32B sectors on cs.
    {
        int e = t >> 1;
        int h = t & 1;
        bool valid = (e0 + e) < E;
        float xs = valid ? __ldg(&g_xsum[e0 + e]) : 0.f;
        const float4* crow = (const float4*)(cs + (size_t)(e0 + e) * RDIM);
        char* ah = smp + SM_AH + e * 128;
        char* al = smp + SM_AL + e * 128;
        u32 sx = (u32)(e & 7) << 4;
        #pragma unroll
        for (int j = 0; j < 8; j++) {
            int q = h + 2 * j;                 // float4 index: r = 4q..4q+3
            float4 c = valid ? crow[q] : make_float4(1.f, 1.f, 1.f, 1.f);
            float a0 = xs * frcp(c.x), a1 = xs * frcp(c.y);
            float a2 = xs * frcp(c.z), a3 = xs * frcp(c.w);
            __nv_bfloat162 h01 = __floats2bfloat162_rn(a0, a1);
            __nv_bfloat162 h23 = __floats2bfloat162_rn(a2, a3);
            __nv_bfloat162 l01 = __floats2bfloat162_rn(
                a0 - __bfloat162float(h01.x), a1 - __bfloat162float(h01.y));
            __nv_bfloat162 l23 = __floats2bfloat162_rn(
                a2 - __bfloat162float(h23.x), a3 - __bfloat162float(h23.y));
            u32 offs = ((u32)(8 * q)) ^ sx;    // 8B chunk, swizzle XOR bits 4-6
            *(uint2*)(ah + offs) = make_uint2(*(u32*)&h01, *(u32*)&h23);
            *(uint2*)(al + offs) = make_uint2(*(u32*)&l01, *(u32*)&l23);
        }
    }
    __syncthreads();

    // --- MMA mainloop ---
    int wm = warp & 3, wn = warp >> 2;
    u32 a_hi = smem_u32(smp + SM_AH), a_lo = smem_u32(smp + SM_AL);
    u32 b_hi = smem_u32(smp + SM_BH), b_lo = smem_u32(smp + SM_BL);

    #pragma unroll 1
    for (int h = 0; h < 2; h++) {
        float d[2][8][4];
        #pragma unroll
        for (int mb = 0; mb < 2; mb++)
            #pragma unroll
            for (int nb = 0; nb < 8; nb++)
                #pragma unroll
                for (int q = 0; q < 4; q++) d[mb][nb][q] = 0.f;

        #pragma unroll
        for (int kb = 0; kb < 4; kb++) {
            // A frags for both splits, held live across the two Bh passes
            u32 ah[2][4], al[2][4];
            #pragma unroll
            for (int mb = 0; mb < 2; mb++) {
                int row  = wm * 32 + mb * 16 + (lane & 15);
                u32 colb = (u32)kb * 32 + ((u32)(lane >> 4) << 4);
                u32 off  = (u32)row * 128 + (colb ^ (((u32)row & 7u) << 4));
                LDSM4(ah[mb][0], ah[mb][1], ah[mb][2], ah[mb][3], a_hi + off);
                LDSM4(al[mb][0], al[mb][1], al[mb][2], al[mb][3], a_lo + off);
            }
            // B hi frags
            u32 b[4][4];
            u32 boff[4];
            #pragma unroll
            for (int q = 0; q < 4; q++) {
                int nrow = wn * 128 + h * 64 + q * 16 + ((lane >> 4) << 3) + (lane & 7);
                u32 colb = (u32)kb * 32 + (((u32)(lane >> 3) & 1u) << 4);
                boff[q]  = (u32)nrow * 128 + (colb ^ (((u32)nrow & 7u) << 4));
                LDSM4(b[q][0], b[q][1], b[q][2], b[q][3], b_hi + boff[q]);
            }
            // pass 0: Ah*Bh ; pass 1: Al*Bh
            #pragma unroll
            for (int mb = 0; mb < 2; mb++)
                #pragma unroll
                for (int nb = 0; nb < 8; nb++)
                    MMA16816(d[mb][nb], ah[mb],
                             b[nb >> 1][(nb & 1) * 2], b[nb >> 1][(nb & 1) * 2 + 1]);
            #pragma unroll
            for (int mb = 0; mb < 2; mb++)
                #pragma unroll
                for (int nb = 0; nb < 8; nb++)
                    MMA16816(d[mb][nb], al[mb],
                             b[nb >> 1][(nb & 1) * 2], b[nb >> 1][(nb & 1) * 2 + 1]);
            // B lo frags (reuse regs), pass 2: Ah*Bl
            #pragma unroll
            for (int q = 0; q < 4; q++)
                LDSM4(b[q][0], b[q][1], b[q][2], b[q][3], b_lo + boff[q]);
            #pragma unroll
            for (int mb = 0; mb < 2; mb++)
                #pragma unroll
                for (int nb = 0; nb < 8; nb++)
                    MMA16816(d[mb][nb], ah[mb],
                             b[nb >> 1][(nb & 1) * 2], b[nb >> 1][(nb & 1) * 2 + 1]);
        }

        // --- epilogue: direct STG.64 (full 32B sectors) ---
        #pragma unroll
        for (int mb = 0; mb < 2; mb++) {
            int r0 = e0 + wm * 32 + mb * 16 + (lane >> 2);
            #pragma unroll
            for (int nb = 0; nb < 8; nb++) {
                int col = wn * 128 + h * 64 + nb * 8 + (lane & 3) * 2;
                if (r0 < E)
                    *(float2*)(out + (size_t)r0 * ODIM + col) =
                        make_float2(d[mb][nb][0], d[mb][nb][1]);
                if (r0 + 8 < E)
                    *(float2*)(out + (size_t)(r0 + 8) * ODIM + col) =
                        make_float2(d[mb][nb][2], d[mb][nb][3]);
            }
        }
    }
}

// ---------------------------------------------------------------------------
extern "C" void kernel_launch(void* const* d_in, const int* in_sizes, int n_in,
                              void* d_out, int out_size) {
    const float* x  = (const float*)d_in[0];
    const float* cs = (const float*)d_in[1];
    const float* W  = (const float*)d_in[2];
    // d_in[3] (edge_index) is mathematically unused by the reference — skipped.
    float* out = (float*)d_out;
    int E = in_sizes[0] / IDIM;

    cudaFuncSetAttribute(rgcn_mma_kernel,
                         cudaFuncAttributeMaxDynamicSharedMemorySize, DYN_SMEM);

    wsum_kernel<<<dim3(RDIM, 4), 256>>>(W);
    xsum_kernel<<<(E + 7) / 8, 256>>>(x, E);
    rgcn_mma_kernel<<<(E + ENT - 1) / ENT, 256, DYN_SMEM>>>(cs, out, E);
}